// round 1
// baseline (speedup 1.0000x reference)
#include <cuda_runtime.h>
#include <math.h>

// Problem dims
#define B_  256
#define T_  336
#define I_  16
#define H_  512
#define L_  256
#define O_  10
#define G4  2048   // 4*H

// Recurrence kernel config
#define NCTA 64
#define NTHR 256           // 8 warps
#define JPC  8             // h-columns per CTA (H_/NCTA)

// ---------------- device scratch (static allocation is allowed) ----------------
__device__ float    d_Wt[G4 * H_];      // sampled Whh, transposed: [gatecol][k]
__device__ float    d_xg[T_ * G4];      // precomputed input projection for b=255
__device__ float    d_hhist[T_ * H_];   // h_t history (also the inter-step broadcast buffer)
__device__ float    d_BLWt[H_ * L_];    // sampled BLW, transposed: [h][l]
__device__ float    d_BLb[L_];          // sampled BLb
__device__ unsigned d_count;            // grid barrier counter (monotonic per launch)

__device__ __forceinline__ float softplusf(float v) {
    return (v > 20.0f) ? v : log1pf(expf(v));
}
__device__ __forceinline__ float sigmoidf(float v) {
    return 1.0f / (1.0f + expf(-v));
}

// ---------------- setup: sample w = mu + softplus(rho)*eps and transpose ----------------
// in: [R x C] row-major, out: [C x R] row-major. R, C multiples of 32.
__global__ void sample_transpose(const float* __restrict__ mu,
                                 const float* __restrict__ rho,
                                 const float* __restrict__ eps,
                                 float* __restrict__ out, int R, int C) {
    __shared__ float tile[32][33];
    const int c0 = blockIdx.x * 32;
    const int r0 = blockIdx.y * 32;
    const int tx = threadIdx.x, ty = threadIdx.y;
    const int idx = (r0 + ty) * C + (c0 + tx);
    tile[ty][tx] = mu[idx] + softplusf(rho[idx]) * eps[idx];
    __syncthreads();
    // element at (r0+tx, c0+ty) -> out[(c0+ty)*R + (r0+tx)]
    out[(c0 + ty) * R + (r0 + tx)] = tile[tx][ty];
}

// ---------------- setup: BLb sampling + barrier reset ----------------
__global__ void setup_misc(const float* __restrict__ blb_mu,
                           const float* __restrict__ blb_rho,
                           const float* __restrict__ eps_blb) {
    const int t = threadIdx.x;
    if (t < L_) d_BLb[t] = blb_mu[t] + softplusf(blb_rho[t]) * eps_blb[t];
    if (t == 0) d_count = 0u;
}

// ---------------- setup: xg[t][g] = b + sum_i (x[255,t,i]*drop_x[255,t,i]) * Wih[i][g] ----------------
// grid: G4/256 blocks x 256 threads; each thread owns one gate column g.
__global__ void compute_xg(const float* __restrict__ x,
                           const float* __restrict__ drop_x,
                           const float* __restrict__ wih_mu,
                           const float* __restrict__ wih_rho,
                           const float* __restrict__ eps_wih,
                           const float* __restrict__ b_mu,
                           const float* __restrict__ b_rho,
                           const float* __restrict__ eps_b) {
    const int g = blockIdx.x * blockDim.x + threadIdx.x;
    float w[I_];
#pragma unroll
    for (int i = 0; i < I_; i++) {
        const int idx = i * G4 + g;
        w[i] = wih_mu[idx] + softplusf(wih_rho[idx]) * eps_wih[idx];
    }
    const float bs = b_mu[g] + softplusf(b_rho[g]) * eps_b[g];
    const float* xrow = x      + (size_t)255 * T_ * I_;
    const float* drow = drop_x + (size_t)255 * T_ * I_;
    for (int t = 0; t < T_; t++) {
        float acc = bs;
#pragma unroll
        for (int i = 0; i < I_; i++)
            acc = fmaf(xrow[t * I_ + i] * drow[t * I_ + i], w[i], acc);
        d_xg[t * G4 + g] = acc;
    }
}

// ---------------- recurrence: persistent kernel, batch row 255 only ----------------
__global__ void __launch_bounds__(NTHR, 1) lstm_recurrence() {
    const int warp = threadIdx.x >> 5;
    const int lane = threadIdx.x & 31;
    const int j    = blockIdx.x * JPC + warp;   // owned h-column, 0..511

    // Register-resident weights: W[c][kk] = Whh[k = kk*32+lane][col = j + c*512]
    float W0[16], W1[16], W2[16], W3[16];
#pragma unroll
    for (int kk = 0; kk < 16; kk++) {
        const int k = kk * 32 + lane;
        W0[kk] = d_Wt[(j          ) * H_ + k];
        W1[kk] = d_Wt[(j +     H_ ) * H_ + k];
        W2[kk] = d_Wt[(j + 2 * H_ ) * H_ + k];
        W3[kk] = d_Wt[(j + 3 * H_ ) * H_ + k];
    }

    float cstate = 0.0f;   // valid in lane 0 only

#pragma unroll 1
    for (int t = 0; t < T_; t++) {
        // per-lane xg fetch (lanes 0..3 carry the 4 gate preactivation biases)
        float myxg = 0.0f;
        if (lane < 4) myxg = __ldg(&d_xg[t * G4 + j + lane * H_]);

        // load h_{t-1} (L2-resident broadcast buffer), coalesced
        float hreg[16];
        if (t == 0) {
#pragma unroll
            for (int kk = 0; kk < 16; kk++) hreg[kk] = 0.0f;
        } else {
            const float* hprev = d_hhist + (size_t)(t - 1) * H_;
#pragma unroll
            for (int kk = 0; kk < 16; kk++)
                hreg[kk] = __ldcg(hprev + kk * 32 + lane);
        }

        float acc0 = 0.f, acc1 = 0.f, acc2 = 0.f, acc3 = 0.f;
#pragma unroll
        for (int kk = 0; kk < 16; kk++) {
            const float hv = hreg[kk];
            acc0 = fmaf(W0[kk], hv, acc0);
            acc1 = fmaf(W1[kk], hv, acc1);
            acc2 = fmaf(W2[kk], hv, acc2);
            acc3 = fmaf(W3[kk], hv, acc3);
        }
        // butterfly reduce over the warp
#pragma unroll
        for (int off = 16; off > 0; off >>= 1) {
            acc0 += __shfl_xor_sync(0xffffffffu, acc0, off);
            acc1 += __shfl_xor_sync(0xffffffffu, acc1, off);
            acc2 += __shfl_xor_sync(0xffffffffu, acc2, off);
            acc3 += __shfl_xor_sync(0xffffffffu, acc3, off);
        }
        const float xg0 = __shfl_sync(0xffffffffu, myxg, 0);
        const float xg1 = __shfl_sync(0xffffffffu, myxg, 1);
        const float xg2 = __shfl_sync(0xffffffffu, myxg, 2);
        const float xg3 = __shfl_sync(0xffffffffu, myxg, 3);

        if (lane == 0) {
            const float iv = sigmoidf(acc0 + xg0);
            const float fv = sigmoidf(acc1 + xg1);
            const float gv = tanhf  (acc2 + xg2);
            const float ov = sigmoidf(acc3 + xg3);
            cstate = fv * cstate + iv * gv;
            const float hval = ov * tanhf(cstate);
            d_hhist[(size_t)t * H_ + j] = hval;
        }

        // ---- grid barrier (monotonic count, reset in setup_misc each launch) ----
        __syncthreads();
        if (threadIdx.x == 0) {
            __threadfence();                       // release h store
            atomicAdd(&d_count, 1u);
            const unsigned target = (unsigned)NCTA * (unsigned)(t + 1);
            while (*((volatile unsigned*)&d_count) < target) { }
            __threadfence();                       // acquire
        }
        __syncthreads();
    }
}

// ---------------- epilogue: out = (relu((last*drop_h)@BLW^T + BLb) * drop_l) @ lin_w^T ----------------
// last[b'] = hhist[80 + b'].  4 batch rows per block for BLWt reuse.
#define BPB 4
__global__ void epilogue(const float* __restrict__ drop_h,
                         const float* __restrict__ drop_l,
                         const float* __restrict__ lin_w,
                         float* __restrict__ out) {
    __shared__ float hv[BPB][H_];
    __shared__ float ys[BPB][L_];
    const int bp0 = blockIdx.x * BPB;
    const int tid = threadIdx.x;

    for (int e = tid; e < BPB * H_; e += blockDim.x) {
        const int bb = e / H_, h = e % H_;
        const int bp = bp0 + bb;
        hv[bb][h] = d_hhist[(size_t)(80 + bp) * H_ + h] * drop_h[(size_t)bp * H_ + h];
    }
    __syncthreads();

    const int l = tid;   // 256 threads == L_
    float a0 = d_BLb[l], a1 = a0, a2 = a0, a3 = a0;
    for (int h = 0; h < H_; h++) {
        const float w = d_BLWt[h * L_ + l];
        a0 = fmaf(hv[0][h], w, a0);
        a1 = fmaf(hv[1][h], w, a1);
        a2 = fmaf(hv[2][h], w, a2);
        a3 = fmaf(hv[3][h], w, a3);
    }
    ys[0][l] = fmaxf(a0, 0.f) * drop_l[(size_t)(bp0 + 0) * L_ + l];
    ys[1][l] = fmaxf(a1, 0.f) * drop_l[(size_t)(bp0 + 1) * L_ + l];
    ys[2][l] = fmaxf(a2, 0.f) * drop_l[(size_t)(bp0 + 2) * L_ + l];
    ys[3][l] = fmaxf(a3, 0.f) * drop_l[(size_t)(bp0 + 3) * L_ + l];
    __syncthreads();

    if (tid < 32) {
        for (int bb = 0; bb < BPB; bb++) {
            for (int o = 0; o < O_; o++) {
                float a = 0.f;
                for (int ll = tid; ll < L_; ll += 32)
                    a = fmaf(ys[bb][ll], lin_w[o * L_ + ll], a);
#pragma unroll
                for (int off = 16; off > 0; off >>= 1)
                    a += __shfl_xor_sync(0xffffffffu, a, off);
                if (tid == 0) out[(size_t)(bp0 + bb) * O_ + o] = a;
            }
        }
    }
}

// ---------------- launcher ----------------
extern "C" void kernel_launch(void* const* d_in, const int* in_sizes, int n_in,
                              void* d_out, int out_size) {
    const float* x        = (const float*)d_in[0];
    const float* drop_x   = (const float*)d_in[1];
    const float* drop_h   = (const float*)d_in[2];
    const float* drop_l   = (const float*)d_in[3];
    const float* wih_mu   = (const float*)d_in[4];
    const float* wih_rho  = (const float*)d_in[5];
    const float* eps_wih  = (const float*)d_in[6];
    const float* whh_mu   = (const float*)d_in[7];
    const float* whh_rho  = (const float*)d_in[8];
    const float* eps_whh  = (const float*)d_in[9];
    const float* b_mu     = (const float*)d_in[10];
    const float* b_rho    = (const float*)d_in[11];
    const float* eps_b    = (const float*)d_in[12];
    const float* blw_mu   = (const float*)d_in[13];
    const float* blw_rho  = (const float*)d_in[14];
    const float* eps_blw  = (const float*)d_in[15];
    const float* blb_mu   = (const float*)d_in[16];
    const float* blb_rho  = (const float*)d_in[17];
    const float* eps_blb  = (const float*)d_in[18];
    const float* lin_w    = (const float*)d_in[19];
    float* out = (float*)d_out;

    float* wt_ptr   = nullptr;
    float* blwt_ptr = nullptr;
    cudaGetSymbolAddress((void**)&wt_ptr,   d_Wt);
    cudaGetSymbolAddress((void**)&blwt_ptr, d_BLWt);

    // setup (all independent of the recurrence; stream order serializes correctly)
    setup_misc<<<1, 256>>>(blb_mu, blb_rho, eps_blb);
    sample_transpose<<<dim3(G4 / 32, H_ / 32), dim3(32, 32)>>>(whh_mu, whh_rho, eps_whh, wt_ptr, H_, G4);
    sample_transpose<<<dim3(H_ / 32, L_ / 32), dim3(32, 32)>>>(blw_mu, blw_rho, eps_blw, blwt_ptr, L_, H_);
    compute_xg<<<G4 / 256, 256>>>(x, drop_x, wih_mu, wih_rho, eps_wih, b_mu, b_rho, eps_b);

    // recurrence (batch row 255 only — see analysis of the reshape-based "last" slice)
    lstm_recurrence<<<NCTA, NTHR>>>();

    // epilogue
    epilogue<<<L_ / BPB, 256>>>(drop_h, drop_l, lin_w, out);
}